// round 11
// baseline (speedup 1.0000x reference)
#include <cuda_runtime.h>
#include <cuda_bf16.h>
#include <cstdint>

// ---------------- problem constants ----------------
#define IN_F   1024
#define NCLS   50257
#define NROWS  8192
#define CUT1   4000
#define CUT2   20000

// rearranged class layout inside g_w / g_bias:
//   [0,4000) shortlist | [4000,4002) tails | [4002,4096) pad
//   [4096,20096) cluster1 | [20096,50353) cluster2 | [50353,50432) pad
#define HEADN  4096
#define C1OFF  4096
#define C1N    16000
#define C2OFF  20096
#define C2N    30336
#define NPAD   50432

// ---------------- GEMM tiling (int8) ----------------
#define BM 128
#define BN 128
#define BKB 128                   // K-bytes per slab = 128 int8 elems
#define KIT (IN_F / BKB)          // 8
#define MT_MAX (NROWS / BM)       // 64

#define A_BYTES (BM * BKB)        // 16384
#define B_BYTES (BN * BKB)        // 16384
#define SM_PART (4 * A_BYTES)     // 65536
#define SM_RID  (SM_PART + BM * 4)
#define SM_TOTAL (SM_RID + BM * 4)

// quantization: x*24, w*1280 -> acc scale 30720
#define SX 24.0f
#define SW 1280.0f
#define INV_S (1.0f / (SX * SW))

// ---------------- device scratch ----------------
__device__ uint8_t g_w[(size_t)NPAD * IN_F];    // s8, scaled x1280
__device__ uint8_t g_x[(size_t)NROWS * IN_F];   // s8, scaled x24
__device__ float g_bias[NPAD];
__device__ float g_sumexp[3][NROWS];
__device__ float g_tlogit[NROWS];
__device__ float g_taillog[2][NROWS];
__device__ int   g_rows1[NROWS + BM];
__device__ int   g_rows2[NROWS + BM];
__device__ int   g_cnt[2];

// ---------------- int8 pack helper (byte0 = first value) ----------------
__device__ __forceinline__ uint32_t q4i(float4 v, float s) {
    int a = __float2int_rn(v.x * s), b = __float2int_rn(v.y * s);
    int c = __float2int_rn(v.z * s), d = __float2int_rn(v.w * s);
    a = max(-127, min(127, a)); b = max(-127, min(127, b));
    c = max(-127, min(127, c)); d = max(-127, min(127, d));
    return (uint32_t)(a & 0xFF) | ((uint32_t)(b & 0xFF) << 8) |
           ((uint32_t)(c & 0xFF) << 16) | ((uint32_t)(d & 0xFF) << 24);
}

// ---------------- kernel 0: zero counters / accumulators / row lists ----------------
__global__ void k_zero() {
    const int tid = blockIdx.x * blockDim.x + threadIdx.x;
    const int stride = gridDim.x * blockDim.x;
    for (int i = tid; i < 3 * NROWS; i += stride) ((float*)g_sumexp)[i] = 0.0f;
    for (int i = tid; i < NROWS + BM; i += stride) { g_rows1[i] = 0; g_rows2[i] = 0; }
    if (tid < 2) g_cnt[tid] = 0;
}

// ---------------- kernel 0b: bucket rows by target cluster ----------------
__global__ void k_bucket(const int* __restrict__ tgt) {
    const int r = blockIdx.x * blockDim.x + threadIdx.x;
    if (r >= NROWS) return;
    const int t = tgt[r];
    const int cl = (t >= CUT1) + (t >= CUT2);
    if (cl == 1)      g_rows1[atomicAdd(&g_cnt[0], 1)] = r;
    else if (cl == 2) g_rows2[atomicAdd(&g_cnt[1], 1)] = r;
}

// ---------------- kernel 1: quantize to int8 (rearranged), build bias ----------------
__global__ void k_prep(const float* __restrict__ w, const float* __restrict__ x,
                       const float* __restrict__ tailv, const float* __restrict__ tailb,
                       const float* __restrict__ bias) {
    const int64_t stride = (int64_t)gridDim.x * blockDim.x;
    const int64_t tid = (int64_t)blockIdx.x * blockDim.x + threadIdx.x;
    const int Q = IN_F / 4;   // float4 per row

    // weight rows -> rearranged slots, scaled x1280
    const float4* w4 = (const float4*)w;
    const int64_t n4w = (int64_t)NCLS * Q;
    for (int64_t i = tid; i < n4w; i += stride) {
        int64_t r = i / Q, c = i - r * Q;
        int64_t dr = (r < CUT1) ? r : r + 96;
        ((uint32_t*)g_w)[dr * Q + c] = q4i(w4[i], SW);
    }
    // tail vectors -> rows 4000, 4001
    const float4* t4 = (const float4*)tailv;
    uint32_t* dt = (uint32_t*)(g_w + (size_t)CUT1 * IN_F);
    for (int64_t i = tid; i < 2 * Q; i += stride) dt[i] = q4i(t4[i], SW);
    // zero pad rows [4002,4096) and [50353,50432)
    uint32_t* z1 = (uint32_t*)(g_w + (size_t)4002 * IN_F);
    for (int64_t i = tid; i < (int64_t)94 * IN_F / 4; i += stride) z1[i] = 0u;
    uint32_t* z2 = (uint32_t*)(g_w + (size_t)50353 * IN_F);
    for (int64_t i = tid; i < (int64_t)79 * IN_F / 4; i += stride) z2[i] = 0u;
    // input -> int8, scaled x24
    const float4* x4 = (const float4*)x;
    const int64_t n4x = (int64_t)NROWS * Q;
    for (int64_t i = tid; i < n4x; i += stride)
        ((uint32_t*)g_x)[i] = q4i(x4[i], SX);
    // rearranged bias (pads -> -1e4 so exp == 0)
    for (int64_t i = tid; i < NPAD; i += stride) {
        float b;
        if (i < CUT1)            b = bias[i];
        else if (i < CUT1 + 2)   b = tailb[i - CUT1];
        else if (i < HEADN)      b = -10000.0f;
        else if (i < 50353)      b = bias[i - 96];
        else                     b = -10000.0f;
        g_bias[i] = b;
    }
}

// ---------------- kernel 2: exact fp32 per-row dots ----------------
__global__ void k_dots(const float* __restrict__ x, const int* __restrict__ tgt,
                       const float* __restrict__ w, const float* __restrict__ bias,
                       const float* __restrict__ tailv, const float* __restrict__ tailb) {
    const int warp = (blockIdx.x * blockDim.x + threadIdx.x) >> 5;
    const int lane = threadIdx.x & 31;
    if (warp >= NROWS) return;
    const int t = tgt[warp];
    const float4* xr = (const float4*)(x + (size_t)warp * IN_F);
    const float4* wr = (const float4*)(w + (size_t)t * IN_F);
    const float4* u0 = (const float4*)tailv;
    const float4* u1 = (const float4*)(tailv + IN_F);
    float a0 = 0.f, a1 = 0.f, a2 = 0.f;
    for (int k = lane; k < IN_F / 4; k += 32) {
        float4 xv = xr[k], wv = wr[k], v0 = u0[k], v1 = u1[k];
        a0 += xv.x * wv.x + xv.y * wv.y + xv.z * wv.z + xv.w * wv.w;
        a1 += xv.x * v0.x + xv.y * v0.y + xv.z * v0.z + xv.w * v0.w;
        a2 += xv.x * v1.x + xv.y * v1.y + xv.z * v1.z + xv.w * v1.w;
    }
    #pragma unroll
    for (int o = 16; o; o >>= 1) {
        a0 += __shfl_xor_sync(0xFFFFFFFFu, a0, o);
        a1 += __shfl_xor_sync(0xFFFFFFFFu, a1, o);
        a2 += __shfl_xor_sync(0xFFFFFFFFu, a2, o);
    }
    if (lane == 0) {
        g_tlogit[warp]     = a0 + bias[t];
        g_taillog[0][warp] = a1 + tailb[0];
        g_taillog[1][warp] = a2 + tailb[1];
    }
}

// ---------------- mma helpers ----------------
__device__ __forceinline__ void mma_s8(int* c, const uint32_t* a, const uint32_t* b) {
    asm volatile(
        "mma.sync.aligned.m16n8k32.row.col.s32.s8.s8.s32 "
        "{%0,%1,%2,%3},{%4,%5,%6,%7},{%8,%9},{%0,%1,%2,%3};"
        : "+r"(c[0]), "+r"(c[1]), "+r"(c[2]), "+r"(c[3])
        : "r"(a[0]), "r"(a[1]), "r"(a[2]), "r"(a[3]), "r"(b[0]), "r"(b[1]));
}
__device__ __forceinline__ void ldmx4(uint32_t* r, uint32_t addr) {
    asm volatile("ldmatrix.sync.aligned.m8n8.x4.shared.b16 {%0,%1,%2,%3}, [%4];"
                 : "=r"(r[0]), "=r"(r[1]), "=r"(r[2]), "=r"(r[3]) : "r"(addr));
}
__device__ __forceinline__ void cp16(uint32_t dst, const void* src) {
    asm volatile("cp.async.cg.shared.global [%0], [%1], 16;" :: "r"(dst), "l"(src));
}

// ---------------- kernel 3: int8 IMMA GEMM + fused exp-sum epilogue ----------------
// mode: 0 = head (all rows, cols [0,4096)), 1 = cluster1, 2 = cluster2
__global__ void __launch_bounds__(256, 2) k_gemm(int mode) {
    const int mtile = blockIdx.x, ntile = blockIdx.y;
    const int* rowlist = (mode == 1) ? g_rows1 : (mode == 2) ? g_rows2 : nullptr;
    const int count = (mode == 0) ? NROWS : g_cnt[mode - 1];
    if (mtile * BM >= count) return;
    const int coloff = (mode == 0) ? 0 : (mode == 1) ? C1OFF : C2OFF;

    extern __shared__ char smem[];
    const uint32_t sbase = (uint32_t)__cvta_generic_to_shared(smem);
    float* sm_part = (float*)(smem + SM_PART);    // [128]
    int*   rid_sm  = (int*)(smem + SM_RID);       // [128]
    const int tid = threadIdx.x;
    const int wid = tid >> 5, lane = tid & 31;
    const int warpM = wid & 1, warpN = wid >> 1;

    if (tid < BM) {
        rid_sm[tid] = rowlist ? rowlist[mtile * BM + tid] : (mtile * BM + tid);
        sm_part[tid] = 0.f;
    }
    __syncthreads();

    const uint8_t* gB = g_w + (size_t)(coloff + ntile * BN) * IN_F;

    int c[4][4][4] = {};

    // each k-slab: 128 rows x 128 bytes (=128 int8 elems), SW128 swizzle
    auto load_tiles = [&](int it, int buf) {
        const int kbase = it * BKB;
        const uint32_t abuf = sbase + buf * A_BYTES;
        const uint32_t bbuf = sbase + 2 * A_BYTES + buf * B_BYTES;
        #pragma unroll
        for (int i = 0; i < 4; ++i) {
            int idx = tid + i * 256;
            int r = idx >> 3, ch = idx & 7;
            uint32_t off = r * 128 + ((ch ^ (r & 7)) << 4);
            cp16(abuf + off, g_x + (size_t)rid_sm[r] * IN_F + kbase + ch * 16);
            cp16(bbuf + off, gB + (size_t)r * IN_F + kbase + ch * 16);
        }
    };

    load_tiles(0, 0);
    asm volatile("cp.async.commit_group;");

    const int g = lane >> 3, lr = lane & 7;

    for (int it = 0; it < KIT; ++it) {
        const int cur = it & 1;
        if (it + 1 < KIT) {
            load_tiles(it + 1, cur ^ 1);
            asm volatile("cp.async.commit_group;");
            asm volatile("cp.async.wait_group 1;");
        } else {
            asm volatile("cp.async.wait_group 0;");
        }
        __syncthreads();

        const uint32_t abuf = sbase + cur * A_BYTES;
        const uint32_t bbuf = sbase + 2 * A_BYTES + cur * B_BYTES;
        // 4 mma k-steps per slab, each k32 int8 = 32 bytes = 2 x 16B chunks
        #pragma unroll
        for (int ks = 0; ks < 4; ++ks) {
            uint32_t b[4][2];
            #pragma unroll
            for (int np = 0; np < 2; ++np) {
                int row = warpN * 32 + np * 16 + ((g >> 1) << 3) + lr;
                int ch = ks * 2 + (g & 1);
                uint32_t addr = bbuf + row * 128 + ((ch ^ (row & 7)) << 4);
                uint32_t r4[4];
                ldmx4(r4, addr);
                b[np * 2][0] = r4[0]; b[np * 2][1] = r4[1];
                b[np * 2 + 1][0] = r4[2]; b[np * 2 + 1][1] = r4[3];
            }
            #pragma unroll
            for (int mt = 0; mt < 4; ++mt) {
                int row = warpM * 64 + mt * 16 + ((g & 1) << 3) + lr;
                int ch = ks * 2 + (g >> 1);
                uint32_t addr = abuf + row * 128 + ((ch ^ (row & 7)) << 4);
                uint32_t a[4];
                ldmx4(a, addr);
                #pragma unroll
                for (int nt = 0; nt < 4; ++nt)
                    mma_s8(c[mt][nt], a, b[nt]);
            }
        }
        __syncthreads();
    }

    // ---- epilogue: single-segment exp-sum per row (unscale by 1/30720) ----
    float bias_r[4][2];
    #pragma unroll
    for (int nt = 0; nt < 4; ++nt) {
        int c0 = coloff + ntile * BN + warpN * 32 + nt * 8 + (lane & 3) * 2;
        bias_r[nt][0] = g_bias[c0];
        bias_r[nt][1] = g_bias[c0 + 1];
    }

    #pragma unroll
    for (int mt = 0; mt < 4; ++mt) {
        float s0 = 0.f, s1 = 0.f;
        #pragma unroll
        for (int nt = 0; nt < 4; ++nt) {
            s0 += __expf(fmaf((float)c[mt][nt][0], INV_S, bias_r[nt][0]))
                + __expf(fmaf((float)c[mt][nt][1], INV_S, bias_r[nt][1]));
            s1 += __expf(fmaf((float)c[mt][nt][2], INV_S, bias_r[nt][0]))
                + __expf(fmaf((float)c[mt][nt][3], INV_S, bias_r[nt][1]));
        }
        #pragma unroll
        for (int rr = 0; rr < 2; ++rr) {
            float v = rr ? s1 : s0;
            v += __shfl_xor_sync(0xFFFFFFFFu, v, 1);
            v += __shfl_xor_sync(0xFFFFFFFFu, v, 2);
            if ((lane & 3) == 0) {
                int row = warpM * 64 + mt * 16 + (lane >> 2) + rr * 8;
                atomicAdd(&sm_part[row], v);
            }
        }
    }
    __syncthreads();
    if (tid < BM && mtile * BM + tid < count) {
        float* seg = (mode == 0) ? g_sumexp[0] : (mode == 1) ? g_sumexp[1] : g_sumexp[2];
        atomicAdd(&seg[rid_sm[tid]], sm_part[tid]);
    }
}

// ---------------- kernel 4: assemble per-row output ----------------
__global__ void k_final(const int* __restrict__ tgt, float* __restrict__ out) {
    const int r = blockIdx.x * blockDim.x + threadIdx.x;
    if (r >= NROWS) return;
    const int t = tgt[r];
    const int cl = (t >= CUT1) + (t >= CUT2);
    const float head_lse = logf(g_sumexp[0][r]);
    float res;
    if (cl == 0) {
        res = g_tlogit[r] - head_lse;
    } else {
        res = (g_taillog[cl - 1][r] - head_lse) + (g_tlogit[r] - logf(g_sumexp[cl][r]));
    }
    out[r] = res;
}

// ---------------- kernel 5: loss = mean(-output) ----------------
__global__ void k_loss(const float* __restrict__ oin, float* __restrict__ out, int out_size) {
    __shared__ float red[32];
    const int tid = threadIdx.x;
    float s = 0.f;
    for (int i = tid; i < NROWS; i += blockDim.x) s += oin[i];
    #pragma unroll
    for (int o = 16; o; o >>= 1) s += __shfl_xor_sync(0xFFFFFFFFu, s, o);
    if ((tid & 31) == 0) red[tid >> 5] = s;
    __syncthreads();
    if (tid < 32) {
        s = (tid < (int)(blockDim.x >> 5)) ? red[tid] : 0.f;
        #pragma unroll
        for (int o = 16; o; o >>= 1) s += __shfl_xor_sync(0xFFFFFFFFu, s, o);
        if (tid == 0 && out_size > NROWS) out[NROWS] = -s / (float)NROWS;
    }
}

// ---------------- launcher ----------------
extern "C" void kernel_launch(void* const* d_in, const int* in_sizes, int n_in,
                              void* d_out, int out_size) {
    const float* input  = (const float*)d_in[0];
    const int*   target = (const int*)d_in[1];
    const float* weight = (const float*)d_in[2];
    const float* bias   = (const float*)d_in[3];
    const float* tailv  = (const float*)d_in[4];
    const float* tailb  = (const float*)d_in[5];
    float* out = (float*)d_out;

    cudaFuncSetAttribute(k_gemm, cudaFuncAttributeMaxDynamicSharedMemorySize, SM_TOTAL);

    k_zero<<<64, 256>>>();
    k_bucket<<<NROWS / 256, 256>>>(target);
    k_prep<<<1024, 256>>>(weight, input, tailv, tailb, bias);
    k_dots<<<NROWS / 8, 256>>>(input, target, weight, bias, tailv, tailb);

    dim3 ghead(MT_MAX, HEADN / BN);          // 64 x 32
    dim3 gc1(MT_MAX, C1N / BN);              // 64 x 125 (early-exit on count)
    dim3 gc2(MT_MAX, C2N / BN);              // 64 x 237 (early-exit on count)
    k_gemm<<<ghead, 256, SM_TOTAL>>>(0);
    k_gemm<<<gc1,   256, SM_TOTAL>>>(1);
    k_gemm<<<gc2,   256, SM_TOTAL>>>(2);

    k_final<<<NROWS / 256, 256>>>(target, out);
    k_loss<<<1, 1024>>>(out, out, out_size);
}

// round 15
// speedup vs baseline: 2.7393x; 2.7393x over previous
#include <cuda_runtime.h>
#include <cuda_bf16.h>
#include <cstdint>

// ---------------- problem constants ----------------
#define IN_F   1024
#define NCLS   50257
#define NROWS  8192
#define CUT1   4000
#define CUT2   20000

// rearranged class layout inside g_w / g_bias:
//   [0,4000) shortlist | [4000,4002) tails | [4002,4096) pad
//   [4096,20096) cluster1 | [20096,50353) cluster2 | [50353,50432) pad
#define HEADN  4096
#define C1OFF  4096
#define C1N    16000
#define C2OFF  20096
#define C2N    30336
#define NPAD   50432

// ---------------- GEMM tiling ----------------
#define BM 128
#define BN 128
#define BK 64
#define KIT (IN_F / BK)           // 16
#define MT_MAX (NROWS / BM)       // 64

// fused 1D tile enumeration (mtile fastest within each segment)
#define HEAD_TILES (MT_MAX * (HEADN / BN))   // 64*32  = 2048
#define C1_TILES   (MT_MAX * (C1N / BN))     // 64*125 = 8000
#define C2_TILES   (MT_MAX * (C2N / BN))     // 64*237 = 15168
#define ALL_TILES  (HEAD_TILES + C1_TILES + C2_TILES)  // 25216

#define A_BYTES (BM * BK * 2)     // 16384
#define B_BYTES (BN * BK * 2)     // 16384
#define STAGE_BYTES (A_BYTES + B_BYTES)
#define SM_PART (3 * STAGE_BYTES)            // 98304
#define SM_RID  (SM_PART + BM * 4)
#define SM_TOTAL (SM_RID + BM * 4)           // 99328

// ---------------- device scratch ----------------
__device__ __nv_bfloat16 g_w[(size_t)NPAD * IN_F];
__device__ __nv_bfloat16 g_x[(size_t)NROWS * IN_F];
__device__ float g_bias[NPAD];
__device__ float g_sumexp[3][NROWS];
__device__ float g_tlogit[NROWS];
__device__ float g_taillog[2][NROWS];
__device__ int   g_rows1[NROWS + BM];
__device__ int   g_rows2[NROWS + BM];
__device__ int   g_cnt[2];

// ---------------- kernel 0: zero counters / accumulators / row lists ----------------
__global__ void k_zero() {
    const int tid = blockIdx.x * blockDim.x + threadIdx.x;
    const int stride = gridDim.x * blockDim.x;
    for (int i = tid; i < 3 * NROWS; i += stride) ((float*)g_sumexp)[i] = 0.0f;
    for (int i = tid; i < NROWS + BM; i += stride) { g_rows1[i] = 0; g_rows2[i] = 0; }
    if (tid < 2) g_cnt[tid] = 0;
}

// ---------------- kernel 0b: bucket rows by target cluster ----------------
__global__ void k_bucket(const int* __restrict__ tgt) {
    const int r = blockIdx.x * blockDim.x + threadIdx.x;
    if (r >= NROWS) return;
    const int t = tgt[r];
    const int cl = (t >= CUT1) + (t >= CUT2);
    if (cl == 1)      g_rows1[atomicAdd(&g_cnt[0], 1)] = r;
    else if (cl == 2) g_rows2[atomicAdd(&g_cnt[1], 1)] = r;
}

// ---------------- kernel 1: convert to bf16 (rearranged), build bias ----------------
__global__ void k_prep(const float* __restrict__ w, const float* __restrict__ x,
                       const float* __restrict__ tailv, const float* __restrict__ tailb,
                       const float* __restrict__ bias) {
    const int64_t stride = (int64_t)gridDim.x * blockDim.x;
    const int64_t tid = (int64_t)blockIdx.x * blockDim.x + threadIdx.x;
    const int Q = IN_F / 4;   // float4 per row

    const float4* w4 = (const float4*)w;
    __nv_bfloat162* dw = (__nv_bfloat162*)g_w;
    const int64_t n4w = (int64_t)NCLS * Q;
    for (int64_t i = tid; i < n4w; i += stride) {
        int64_t r = i / Q, c = i - r * Q;
        int64_t dr = (r < CUT1) ? r : r + 96;
        float4 v = w4[i];
        int64_t d = dr * Q + c;
        dw[2 * d]     = __floats2bfloat162_rn(v.x, v.y);
        dw[2 * d + 1] = __floats2bfloat162_rn(v.z, v.w);
    }
    const float4* t4 = (const float4*)tailv;
    __nv_bfloat162* dt = (__nv_bfloat162*)(g_w + (size_t)CUT1 * IN_F);
    for (int64_t i = tid; i < 2 * Q; i += stride) {
        float4 v = t4[i];
        dt[2 * i]     = __floats2bfloat162_rn(v.x, v.y);
        dt[2 * i + 1] = __floats2bfloat162_rn(v.z, v.w);
    }
    uint32_t* z1 = (uint32_t*)(g_w + (size_t)4002 * IN_F);
    for (int64_t i = tid; i < (int64_t)94 * IN_F / 2; i += stride) z1[i] = 0u;
    uint32_t* z2 = (uint32_t*)(g_w + (size_t)50353 * IN_F);
    for (int64_t i = tid; i < (int64_t)79 * IN_F / 2; i += stride) z2[i] = 0u;
    const float4* x4 = (const float4*)x;
    __nv_bfloat162* dx = (__nv_bfloat162*)g_x;
    const int64_t n4x = (int64_t)NROWS * Q;
    for (int64_t i = tid; i < n4x; i += stride) {
        float4 v = x4[i];
        dx[2 * i]     = __floats2bfloat162_rn(v.x, v.y);
        dx[2 * i + 1] = __floats2bfloat162_rn(v.z, v.w);
    }
    for (int64_t i = tid; i < NPAD; i += stride) {
        float b;
        if (i < CUT1)            b = bias[i];
        else if (i < CUT1 + 2)   b = tailb[i - CUT1];
        else if (i < HEADN)      b = -10000.0f;
        else if (i < 50353)      b = bias[i - 96];
        else                     b = -10000.0f;
        g_bias[i] = b;
    }
}

// ---------------- kernel 2: exact fp32 per-row dots ----------------
__global__ void k_dots(const float* __restrict__ x, const int* __restrict__ tgt,
                       const float* __restrict__ w, const float* __restrict__ bias,
                       const float* __restrict__ tailv, const float* __restrict__ tailb) {
    const int warp = (blockIdx.x * blockDim.x + threadIdx.x) >> 5;
    const int lane = threadIdx.x & 31;
    if (warp >= NROWS) return;
    const int t = tgt[warp];
    const float4* xr = (const float4*)(x + (size_t)warp * IN_F);
    const float4* wr = (const float4*)(w + (size_t)t * IN_F);
    const float4* u0 = (const float4*)tailv;
    const float4* u1 = (const float4*)(tailv + IN_F);
    float a0 = 0.f, a1 = 0.f, a2 = 0.f;
    for (int k = lane; k < IN_F / 4; k += 32) {
        float4 xv = xr[k], wv = wr[k], v0 = u0[k], v1 = u1[k];
        a0 += xv.x * wv.x + xv.y * wv.y + xv.z * wv.z + xv.w * wv.w;
        a1 += xv.x * v0.x + xv.y * v0.y + xv.z * v0.z + xv.w * v0.w;
        a2 += xv.x * v1.x + xv.y * v1.y + xv.z * v1.z + xv.w * v1.w;
    }
    #pragma unroll
    for (int o = 16; o; o >>= 1) {
        a0 += __shfl_xor_sync(0xFFFFFFFFu, a0, o);
        a1 += __shfl_xor_sync(0xFFFFFFFFu, a1, o);
        a2 += __shfl_xor_sync(0xFFFFFFFFu, a2, o);
    }
    if (lane == 0) {
        g_tlogit[warp]     = a0 + bias[t];
        g_taillog[0][warp] = a1 + tailb[0];
        g_taillog[1][warp] = a2 + tailb[1];
    }
}

// ---------------- mma.sync helpers ----------------
__device__ __forceinline__ void mma16816(float* c, const uint32_t* a, const uint32_t* b) {
    asm volatile(
        "mma.sync.aligned.m16n8k16.row.col.f32.bf16.bf16.f32 "
        "{%0,%1,%2,%3},{%4,%5,%6,%7},{%8,%9},{%0,%1,%2,%3};"
        : "+f"(c[0]), "+f"(c[1]), "+f"(c[2]), "+f"(c[3])
        : "r"(a[0]), "r"(a[1]), "r"(a[2]), "r"(a[3]), "r"(b[0]), "r"(b[1]));
}
__device__ __forceinline__ void ldmx4(uint32_t* r, uint32_t addr) {
    asm volatile("ldmatrix.sync.aligned.m8n8.x4.shared.b16 {%0,%1,%2,%3}, [%4];"
                 : "=r"(r[0]), "=r"(r[1]), "=r"(r[2]), "=r"(r[3]) : "r"(addr));
}
__device__ __forceinline__ void cp16(uint32_t dst, const void* src) {
    asm volatile("cp.async.cg.shared.global [%0], [%1], 16;" :: "r"(dst), "l"(src));
}

// ---------------- kernel 3: fused bf16 HMMA GEMM (all segments, one launch) ----------------
__global__ void __launch_bounds__(256, 2) k_gemm() {
    const int bid = blockIdx.x;
    int mode, mtile, ntile;
    if (bid < HEAD_TILES)                  { mode = 0; mtile = bid & 63; ntile = bid >> 6; }
    else if (bid < HEAD_TILES + C1_TILES)  { int b = bid - HEAD_TILES; mode = 1; mtile = b & 63; ntile = b >> 6; }
    else                                   { int b = bid - HEAD_TILES - C1_TILES; mode = 2; mtile = b & 63; ntile = b >> 6; }

    const int* rowlist = (mode == 1) ? g_rows1 : (mode == 2) ? g_rows2 : nullptr;
    const int count = (mode == 0) ? NROWS : g_cnt[mode - 1];
    if (mtile * BM >= count) return;
    const int coloff = (mode == 0) ? 0 : (mode == 1) ? C1OFF : C2OFF;

    extern __shared__ char smem[];
    const uint32_t sbase = (uint32_t)__cvta_generic_to_shared(smem);
    float* sm_part = (float*)(smem + SM_PART);    // [128]
    int*   rid_sm  = (int*)(smem + SM_RID);       // [128]
    const int tid = threadIdx.x;
    const int wid = tid >> 5, lane = tid & 31;
    const int warpM = wid & 1, warpN = wid >> 1;

    if (tid < BM) {
        rid_sm[tid] = rowlist ? rowlist[mtile * BM + tid] : (mtile * BM + tid);
        sm_part[tid] = 0.f;
    }
    __syncthreads();

    const __nv_bfloat16* gB = g_w + (size_t)(coloff + ntile * BN) * IN_F;

    float c[4][4][4] = {};

    auto load_tiles = [&](int it, int buf) {
        const int kbase = it * BK;
        const uint32_t abuf = sbase + buf * STAGE_BYTES;
        const uint32_t bbuf = abuf + A_BYTES;
        #pragma unroll
        for (int i = 0; i < 4; ++i) {
            int idx = tid + i * 256;
            int r = idx >> 3, ch = idx & 7;
            uint32_t off = r * 128 + ((ch ^ (r & 7)) << 4);
            cp16(abuf + off, g_x + (size_t)rid_sm[r] * IN_F + kbase + ch * 8);
            cp16(bbuf + off, gB + (size_t)r * IN_F + kbase + ch * 8);
        }
    };

    // 3-stage pipeline: preload stages 0,1 (FIFO groups s0, s1)
    load_tiles(0, 0);
    asm volatile("cp.async.commit_group;");
    load_tiles(1, 1);
    asm volatile("cp.async.commit_group;");

    const int g = lane >> 3, lr = lane & 7;

    int buf = 0;
    for (int it = 0; it < KIT; ++it) {
        // 1) my copies of stage `it` complete (pending set is {s_it, s_it+1})
        if (it + 1 < KIT) asm volatile("cp.async.wait_group 1;");
        else              asm volatile("cp.async.wait_group 0;");
        // 2) EVERYONE's copies of stage `it` visible; all reads of stage it-1 done
        __syncthreads();
        // 3) refill the slot stage it-1 just vacated
        if (it + 2 < KIT) {
            int nb = buf + 2; if (nb >= 3) nb -= 3;
            load_tiles(it + 2, nb);
            asm volatile("cp.async.commit_group;");
        }
        // 4) compute on stage `it`
        const uint32_t abuf = sbase + buf * STAGE_BYTES;
        const uint32_t bbuf = abuf + A_BYTES;
        #pragma unroll
        for (int ks = 0; ks < 4; ++ks) {
            uint32_t b[4][2];
            #pragma unroll
            for (int np = 0; np < 2; ++np) {
                int row = warpN * 32 + np * 16 + ((g >> 1) << 3) + lr;
                int ch = ks * 2 + (g & 1);
                uint32_t addr = bbuf + row * 128 + ((ch ^ (row & 7)) << 4);
                uint32_t r4[4];
                ldmx4(r4, addr);
                b[np * 2][0] = r4[0]; b[np * 2][1] = r4[1];
                b[np * 2 + 1][0] = r4[2]; b[np * 2 + 1][1] = r4[3];
            }
            #pragma unroll
            for (int mt = 0; mt < 4; ++mt) {
                int row = warpM * 64 + mt * 16 + ((g & 1) << 3) + lr;
                int ch = ks * 2 + (g >> 1);
                uint32_t addr = abuf + row * 128 + ((ch ^ (row & 7)) << 4);
                uint32_t a[4];
                ldmx4(a, addr);
                #pragma unroll
                for (int nt = 0; nt < 4; ++nt)
                    mma16816(c[mt][nt], a, b[nt]);
            }
        }
        if (++buf >= 3) buf = 0;
    }

    // ---- epilogue: single-segment exp-sum per row ----
    float bias_r[4][2];
    #pragma unroll
    for (int nt = 0; nt < 4; ++nt) {
        int c0 = coloff + ntile * BN + warpN * 32 + nt * 8 + (lane & 3) * 2;
        bias_r[nt][0] = g_bias[c0];
        bias_r[nt][1] = g_bias[c0 + 1];
    }

    #pragma unroll
    for (int mt = 0; mt < 4; ++mt) {
        float s0 = 0.f, s1 = 0.f;
        #pragma unroll
        for (int nt = 0; nt < 4; ++nt) {
            s0 += __expf(c[mt][nt][0] + bias_r[nt][0]) + __expf(c[mt][nt][1] + bias_r[nt][1]);
            s1 += __expf(c[mt][nt][2] + bias_r[nt][0]) + __expf(c[mt][nt][3] + bias_r[nt][1]);
        }
        #pragma unroll
        for (int rr = 0; rr < 2; ++rr) {
            float v = rr ? s1 : s0;
            v += __shfl_xor_sync(0xFFFFFFFFu, v, 1);
            v += __shfl_xor_sync(0xFFFFFFFFu, v, 2);
            if ((lane & 3) == 0) {
                int row = warpM * 64 + mt * 16 + (lane >> 2) + rr * 8;
                atomicAdd(&sm_part[row], v);
            }
        }
    }
    __syncthreads();
    if (tid < BM && mtile * BM + tid < count) {
        float* seg = (mode == 0) ? g_sumexp[0] : (mode == 1) ? g_sumexp[1] : g_sumexp[2];
        atomicAdd(&seg[rid_sm[tid]], sm_part[tid]);
    }
}

// ---------------- kernel 4: assemble per-row output ----------------
__global__ void k_final(const int* __restrict__ tgt, float* __restrict__ out) {
    const int r = blockIdx.x * blockDim.x + threadIdx.x;
    if (r >= NROWS) return;
    const int t = tgt[r];
    const int cl = (t >= CUT1) + (t >= CUT2);
    const float head_lse = logf(g_sumexp[0][r]);
    float res;
    if (cl == 0) {
        res = g_tlogit[r] - head_lse;
    } else {
        res = (g_taillog[cl - 1][r] - head_lse) + (g_tlogit[r] - logf(g_sumexp[cl][r]));
    }
    out[r] = res;
}

// ---------------- kernel 5: loss = mean(-output) ----------------
__global__ void k_loss(const float* __restrict__ oin, float* __restrict__ out, int out_size) {
    __shared__ float red[32];
    const int tid = threadIdx.x;
    float s = 0.f;
    for (int i = tid; i < NROWS; i += blockDim.x) s += oin[i];
    #pragma unroll
    for (int o = 16; o; o >>= 1) s += __shfl_xor_sync(0xFFFFFFFFu, s, o);
    if ((tid & 31) == 0) red[tid >> 5] = s;
    __syncthreads();
    if (tid < 32) {
        s = (tid < (int)(blockDim.x >> 5)) ? red[tid] : 0.f;
        #pragma unroll
        for (int o = 16; o; o >>= 1) s += __shfl_xor_sync(0xFFFFFFFFu, s, o);
        if (tid == 0 && out_size > NROWS) out[NROWS] = -s / (float)NROWS;
    }
}

// ---------------- launcher ----------------
extern "C" void kernel_launch(void* const* d_in, const int* in_sizes, int n_in,
                              void* d_out, int out_size) {
    const float* input  = (const float*)d_in[0];
    const int*   target = (const int*)d_in[1];
    const float* weight = (const float*)d_in[2];
    const float* bias   = (const float*)d_in[3];
    const float* tailv  = (const float*)d_in[4];
    const float* tailb  = (const float*)d_in[5];
    float* out = (float*)d_out;

    cudaFuncSetAttribute(k_gemm, cudaFuncAttributeMaxDynamicSharedMemorySize, SM_TOTAL);

    k_zero<<<64, 256>>>();
    k_bucket<<<NROWS / 256, 256>>>(target);
    k_prep<<<1024, 256>>>(weight, input, tailv, tailb, bias);
    k_dots<<<NROWS / 8, 256>>>(input, target, weight, bias, tailv, tailb);

    k_gemm<<<ALL_TILES, 256, SM_TOTAL>>>();   // head + cluster1 + cluster2 fused

    k_final<<<NROWS / 256, 256>>>(target, out);
    k_loss<<<1, 1024>>>(out, out, out_size);
}